// round 3
// baseline (speedup 1.0000x reference)
#include <cuda_runtime.h>

#define NN 100000
#define EE 640000
#define GG 64

// ---------------- scratch (static device allocations are allowed) ----------
__device__ __align__(16) float g_deg[NN];
__device__ __align__(16) float g_w[EE];
__device__ __align__(16) float g_P1[NN * 128];
__device__ __align__(16) float g_P2[NN * 128];
__device__ __align__(16) float g_H1[NN * 64];
__device__ __align__(16) float g_H2[NN * 32];
__device__ __align__(16) float g_H3[NN * 16];
__device__ __align__(16) float g_Wc[3 * 128 * 64];
__device__ __align__(16) float g_sc[64];
__device__ __align__(16) float g_sh[64];
__device__ __align__(16) float g_pool[GG * 16 + GG];   // sums then counts

// ---------------- degree + cheb norm ---------------------------------------
__global__ void k_deg(const int* __restrict__ ei) {
    int e = blockIdx.x * blockDim.x + threadIdx.x;
    if (e >= EE) return;
    int s = ei[e], d = ei[EE + e];
    if (s != d) atomicAdd(&g_deg[s], 1.0f);
}

__global__ void k_w(const int* __restrict__ ei) {
    int e = blockIdx.x * blockDim.x + threadIdx.x;
    if (e >= EE) return;
    int s = ei[e], d = ei[EE + e];
    float w = 0.0f;
    if (s != d) {
        float ds = g_deg[s], dd = g_deg[d];
        float is = rsqrtf(ds);                       // ds >= 1 here
        float id = dd > 0.0f ? rsqrtf(dd) : 0.0f;
        w = -is * id;
    }
    g_w[e] = w;
}

// ---------------- sparse propagation: out[dst] += w * in[src] --------------
template <int Fv>
__global__ void __launch_bounds__(256) k_prop(const float* __restrict__ in,
                                              float* __restrict__ out,
                                              const int* __restrict__ ei) {
    constexpr int C = Fv / 4;
    int tid = blockIdx.x * blockDim.x + threadIdx.x;
    if (tid >= EE * C) return;
    int e = tid / C, c = tid % C;
    float w = g_w[e];
    if (w == 0.0f) return;
    int s = ei[e], d = ei[EE + e];
    float4 v = *(const float4*)(in + (size_t)s * Fv + c * 4);
    float rx = w * v.x, ry = w * v.y, rz = w * v.z, rw = w * v.w;
    float* p = out + (size_t)d * Fv + c * 4;
    asm volatile("red.global.add.v4.f32 [%0], {%1,%2,%3,%4};"
                 :: "l"(p), "f"(rx), "f"(ry), "f"(rz), "f"(rw) : "memory");
}

// ---------------- weight/BN prep: fold Cheb recurrence + BN affine ---------
__global__ void k_prep(const float* __restrict__ W, const float* __restrict__ b,
                       const float* __restrict__ g, const float* __restrict__ be,
                       const float* __restrict__ m, const float* __restrict__ v,
                       int Fin, int Fout) {
    int tid = threadIdx.x;
    int tot = Fin * Fout;
    for (int i = tid; i < tot; i += blockDim.x) {
        float w0 = W[i], w1 = W[tot + i], w2 = W[2 * tot + i];
        g_Wc[i]           = w0 - w2;   // A coefficient  (Tx2 = 2*prop(P1) - A)
        g_Wc[tot + i]     = w1;        // P1 coefficient
        g_Wc[2 * tot + i] = 2.0f * w2; // raw prop(P1) coefficient
    }
    if (tid < Fout) {
        float s = g[tid] * rsqrtf(v[tid] + 1e-5f);
        g_sc[tid] = s;
        g_sh[tid] = (b[tid] - m[tid]) * s + be[tid];
    }
}

// ---------------- fused 3-way GEMM + BN + LeakyReLU ------------------------
// H[m, :] = leaky(( [A|P1|P2][m,:] @ Wc ) * sc + sh),  tile 64 x BN, BK=16
template <int BN, int FIN>
__global__ void __launch_bounds__(256) k_gemm(const float* __restrict__ A0,
                                              const float* __restrict__ P1,
                                              const float* __restrict__ P2,
                                              float* __restrict__ H) {
    constexpr int TN = BN / 16;
    __shared__ __align__(16) float As[64][20];
    __shared__ __align__(16) float Bs[16][BN];
    int t = threadIdx.x;
    int tx = t & 15, ty = t >> 4;
    int m0 = blockIdx.x * 64;

    float acc[4][TN];
#pragma unroll
    for (int i = 0; i < 4; i++)
#pragma unroll
        for (int j = 0; j < TN; j++) acc[i][j] = 0.0f;

    int lr = t >> 2;            // A-tile row 0..63
    int lc = (t & 3) * 4;       // A-tile col group {0,4,8,12}
    constexpr int BROW_T = BN / 4;   // float4 per B row
    int mg_l = m0 + lr;

    for (int k0 = 0; k0 < 3 * FIN; k0 += 16) {
        const float* src;
        int col0;
        if (k0 < FIN)            { src = A0; col0 = k0; }
        else if (k0 < 2 * FIN)   { src = P1; col0 = k0 - FIN; }
        else                     { src = P2; col0 = k0 - 2 * FIN; }

        float4 av = make_float4(0.f, 0.f, 0.f, 0.f);
        if (mg_l < NN) av = *(const float4*)(src + (size_t)mg_l * FIN + col0 + lc);
        *(float4*)&As[lr][lc] = av;

        if (t < 16 * BROW_T) {
            int brow = t / BROW_T;
            int bc4 = (t % BROW_T) * 4;
            *(float4*)&Bs[brow][bc4] = *(const float4*)(g_Wc + (k0 + brow) * BN + bc4);
        }
        __syncthreads();

#pragma unroll
        for (int kk = 0; kk < 16; kk++) {
            float a[4], bb[TN];
#pragma unroll
            for (int i = 0; i < 4; i++) a[i] = As[ty + 16 * i][kk];
#pragma unroll
            for (int j = 0; j < TN; j++) bb[j] = Bs[kk][tx + 16 * j];
#pragma unroll
            for (int i = 0; i < 4; i++)
#pragma unroll
                for (int j = 0; j < TN; j++) acc[i][j] += a[i] * bb[j];
        }
        __syncthreads();
    }

#pragma unroll
    for (int j = 0; j < TN; j++) {
        int n = tx + 16 * j;
        float s = g_sc[n], sh = g_sh[n];
#pragma unroll
        for (int i = 0; i < 4; i++) {
            int mg = m0 + ty + 16 * i;
            if (mg < NN) {
                float y = acc[i][j] * s + sh;
                H[(size_t)mg * BN + n] = y > 0.0f ? y : 0.01f * y;
            }
        }
    }
}

// ---------------- global mean pool (batch sorted -> run-length accumulate) -
__global__ void k_pool(const float* __restrict__ H, const int* __restrict__ batch) {
    constexpr int CH = 16;
    int tid = blockIdx.x * blockDim.x + threadIdx.x;
    int n0 = tid * CH;
    if (n0 >= NN) return;
    int n1 = n0 + CH; if (n1 > NN) n1 = NN;

    float acc[16];
#pragma unroll
    for (int f = 0; f < 16; f++) acc[f] = 0.0f;
    float cnt = 0.0f;
    int cur = batch[n0];

    for (int n = n0; n < n1; n++) {
        int b = batch[n];
        if (b != cur) {
#pragma unroll
            for (int f = 0; f < 16; f++) atomicAdd(&g_pool[cur * 16 + f], acc[f]);
            atomicAdd(&g_pool[GG * 16 + cur], cnt);
#pragma unroll
            for (int f = 0; f < 16; f++) acc[f] = 0.0f;
            cnt = 0.0f;
            cur = b;
        }
        const float4* r = (const float4*)(H + (size_t)n * 16);
        float4 r0 = r[0], r1 = r[1], r2 = r[2], r3 = r[3];
        acc[0] += r0.x; acc[1] += r0.y; acc[2] += r0.z; acc[3] += r0.w;
        acc[4] += r1.x; acc[5] += r1.y; acc[6] += r1.z; acc[7] += r1.w;
        acc[8] += r2.x; acc[9] += r2.y; acc[10] += r2.z; acc[11] += r2.w;
        acc[12] += r3.x; acc[13] += r3.y; acc[14] += r3.z; acc[15] += r3.w;
        cnt += 1.0f;
    }
#pragma unroll
    for (int f = 0; f < 16; f++) atomicAdd(&g_pool[cur * 16 + f], acc[f]);
    atomicAdd(&g_pool[GG * 16 + cur], cnt);
}

// ---------------- final linear [G,16] @ [16,2]^T + bias --------------------
__global__ void k_final(const float* __restrict__ lw, const float* __restrict__ lb,
                        float* __restrict__ out) {
    int tid = threadIdx.x;
    if (tid >= GG * 2) return;
    int g = tid >> 1, o = tid & 1;
    float c = g_pool[GG * 16 + g];
    if (c < 1.0f) c = 1.0f;
    float inv = 1.0f / c;
    float s = 0.0f;
#pragma unroll
    for (int f = 0; f < 16; f++)
        s += g_pool[g * 16 + f] * inv * lw[o * 16 + f];
    out[tid] = s + lb[o];
}

// ---------------- host orchestration ---------------------------------------
extern "C" void kernel_launch(void* const* d_in, const int* in_sizes, int n_in,
                              void* d_out, int out_size) {
    (void)in_sizes; (void)n_in; (void)out_size;
    const float* x     = (const float*)d_in[0];
    const int*   ei    = (const int*)d_in[1];
    const int*   batch = (const int*)d_in[2];
    const float* W1 = (const float*)d_in[3],  *b1 = (const float*)d_in[4];
    const float* g1 = (const float*)d_in[5],  *be1 = (const float*)d_in[6];
    const float* m1 = (const float*)d_in[7],  *v1 = (const float*)d_in[8];
    const float* W2 = (const float*)d_in[9],  *b2 = (const float*)d_in[10];
    const float* g2 = (const float*)d_in[11], *be2 = (const float*)d_in[12];
    const float* m2 = (const float*)d_in[13], *v2 = (const float*)d_in[14];
    const float* W3 = (const float*)d_in[15], *b3 = (const float*)d_in[16];
    const float* g3 = (const float*)d_in[17], *be3 = (const float*)d_in[18];
    const float* m3 = (const float*)d_in[19], *v3 = (const float*)d_in[20];
    const float* lw = (const float*)d_in[21], *lb = (const float*)d_in[22];
    float* out = (float*)d_out;

    float *p_deg, *p_P1, *p_P2, *p_H1, *p_H2, *p_H3, *p_pool;
    cudaGetSymbolAddress((void**)&p_deg,  g_deg);
    cudaGetSymbolAddress((void**)&p_P1,   g_P1);
    cudaGetSymbolAddress((void**)&p_P2,   g_P2);
    cudaGetSymbolAddress((void**)&p_H1,   g_H1);
    cudaGetSymbolAddress((void**)&p_H2,   g_H2);
    cudaGetSymbolAddress((void**)&p_H3,   g_H3);
    cudaGetSymbolAddress((void**)&p_pool, g_pool);

    cudaMemsetAsync(p_deg,  0, NN * sizeof(float));
    cudaMemsetAsync(p_pool, 0, (GG * 16 + GG) * sizeof(float));

    int eb = (EE + 255) / 256;
    k_deg<<<eb, 256>>>(ei);
    k_w<<<eb, 256>>>(ei);

    // ----- layer 1: 128 -> 64 -----
    cudaMemsetAsync(p_P1, 0, (size_t)NN * 128 * sizeof(float));
    cudaMemsetAsync(p_P2, 0, (size_t)NN * 128 * sizeof(float));
    k_prep<<<1, 256>>>(W1, b1, g1, be1, m1, v1, 128, 64);
    {
        int total = EE * (128 / 4);
        int gb = (total + 255) / 256;
        k_prop<128><<<gb, 256>>>(x,    p_P1, ei);
        k_prop<128><<<gb, 256>>>(p_P1, p_P2, ei);
    }
    k_gemm<64, 128><<<(NN + 63) / 64, 256>>>(x, p_P1, p_P2, p_H1);

    // ----- layer 2: 64 -> 32 -----
    cudaMemsetAsync(p_P1, 0, (size_t)NN * 64 * sizeof(float));
    cudaMemsetAsync(p_P2, 0, (size_t)NN * 64 * sizeof(float));
    k_prep<<<1, 256>>>(W2, b2, g2, be2, m2, v2, 64, 32);
    {
        int total = EE * (64 / 4);
        int gb = (total + 255) / 256;
        k_prop<64><<<gb, 256>>>(p_H1, p_P1, ei);
        k_prop<64><<<gb, 256>>>(p_P1, p_P2, ei);
    }
    k_gemm<32, 64><<<(NN + 63) / 64, 256>>>(p_H1, p_P1, p_P2, p_H2);

    // ----- layer 3: 32 -> 16 -----
    cudaMemsetAsync(p_P1, 0, (size_t)NN * 32 * sizeof(float));
    cudaMemsetAsync(p_P2, 0, (size_t)NN * 32 * sizeof(float));
    k_prep<<<1, 256>>>(W3, b3, g3, be3, m3, v3, 32, 16);
    {
        int total = EE * (32 / 4);
        int gb = (total + 255) / 256;
        k_prop<32><<<gb, 256>>>(p_H2, p_P1, ei);
        k_prop<32><<<gb, 256>>>(p_P1, p_P2, ei);
    }
    k_gemm<16, 32><<<(NN + 63) / 64, 256>>>(p_H2, p_P1, p_P2, p_H3);

    // ----- pool + classifier -----
    {
        int threads = (NN + 15) / 16;
        int gb = (threads + 255) / 256;
        k_pool<<<gb, 256>>>(p_H3, batch);
    }
    k_final<<<1, 128>>>(lw, lb, out);
}

// round 4
// speedup vs baseline: 1.4072x; 1.4072x over previous
#include <cuda_runtime.h>

#define NN 100000
#define EE 640000
#define GG 64
#define SCAN_BLK 512
#define NBLK ((NN + SCAN_BLK - 1) / SCAN_BLK)   // 196

// ---------------- scratch ---------------------------------------------------
__device__ __align__(16) int   g_degi[NN];        // out-degree (non-loop, by src)
__device__ __align__(16) int   g_cnt[NN];         // in-degree  (non-loop, by dst)
__device__ __align__(16) int   g_incl[NN];        // scan temp
__device__ __align__(16) int   g_bsum[NBLK];
__device__ __align__(16) int   g_rowptr[NN + 1];
__device__ __align__(16) int   g_cursor[NN];
__device__ __align__(16) int   g_csr_src[EE];
__device__ __align__(16) float g_csr_w[EE];
__device__ __align__(16) float g_P1[NN * 128];
__device__ __align__(16) float g_P2[NN * 128];
__device__ __align__(16) float g_H1[NN * 64];
__device__ __align__(16) float g_H2[NN * 32];
__device__ __align__(16) float g_H3[NN * 16];
__device__ __align__(16) float g_Wc[3 * 128 * 64];
__device__ __align__(16) float g_sc[64];
__device__ __align__(16) float g_sh[64];
__device__ __align__(16) float g_pool[GG * 16 + GG];

// ---------------- CSR build -------------------------------------------------
__global__ void k_degcnt(const int* __restrict__ ei) {
    int e = blockIdx.x * blockDim.x + threadIdx.x;
    if (e >= EE) return;
    int s = ei[e], d = ei[EE + e];
    if (s != d) {
        atomicAdd(&g_degi[s], 1);
        atomicAdd(&g_cnt[d], 1);
    }
}

__global__ void k_scan1() {
    __shared__ int sh[SCAN_BLK];
    int i = blockIdx.x * SCAN_BLK + threadIdx.x;
    int v = (i < NN) ? g_cnt[i] : 0;
    sh[threadIdx.x] = v;
    __syncthreads();
#pragma unroll
    for (int off = 1; off < SCAN_BLK; off <<= 1) {
        int t = (threadIdx.x >= off) ? sh[threadIdx.x - off] : 0;
        __syncthreads();
        sh[threadIdx.x] += t;
        __syncthreads();
    }
    if (i < NN) g_incl[i] = sh[threadIdx.x];
    if (threadIdx.x == SCAN_BLK - 1) g_bsum[blockIdx.x] = sh[threadIdx.x];
}

__global__ void k_scan2() {
    __shared__ int sh[256];
    int t = threadIdx.x;
    int v = (t < NBLK) ? g_bsum[t] : 0;
    sh[t] = v;
    __syncthreads();
#pragma unroll
    for (int off = 1; off < 256; off <<= 1) {
        int u = (t >= off) ? sh[t - off] : 0;
        __syncthreads();
        sh[t] += u;
        __syncthreads();
    }
    if (t < NBLK) g_bsum[t] = (t > 0) ? sh[t - 1] : 0;   // exclusive
}

__global__ void k_scan3() {
    int i = blockIdx.x * blockDim.x + threadIdx.x;
    if (i < NN) g_rowptr[i + 1] = g_incl[i] + g_bsum[i / SCAN_BLK];
    if (i == 0) g_rowptr[0] = 0;
}

__global__ void k_fill(const int* __restrict__ ei) {
    int e = blockIdx.x * blockDim.x + threadIdx.x;
    if (e >= EE) return;
    int s = ei[e], d = ei[EE + e];
    if (s == d) return;
    float is = rsqrtf((float)g_degi[s]);          // >= 1 (this edge counts)
    int dd = g_degi[d];
    float id = dd > 0 ? rsqrtf((float)dd) : 0.0f;
    float w = -is * id;
    int pos = atomicAdd(&g_cursor[d], 1);
    g_csr_src[pos] = s;
    g_csr_w[pos] = w;
}

// ---------------- gather propagation: out[i] = sum_e w*in[src[e]] ----------
template <int F>
__global__ void __launch_bounds__(256) k_gather(const float* __restrict__ in,
                                                float* __restrict__ out) {
    int warp = (blockIdx.x * blockDim.x + threadIdx.x) >> 5;
    int lane = threadIdx.x & 31;
    if (warp >= NN) return;
    int r0 = g_rowptr[warp], r1 = g_rowptr[warp + 1];
    constexpr int V = F / 32;
    float acc[V];
#pragma unroll
    for (int i = 0; i < V; i++) acc[i] = 0.0f;

    int j = r0;
    for (; j + 1 < r1; j += 2) {
        int   s0 = __ldg(g_csr_src + j),     s1 = __ldg(g_csr_src + j + 1);
        float w0 = __ldg(g_csr_w + j),       w1 = __ldg(g_csr_w + j + 1);
        const float* p0 = in + (size_t)s0 * F + lane * V;
        const float* p1 = in + (size_t)s1 * F + lane * V;
        if constexpr (V == 4) {
            float4 a = *(const float4*)p0, b = *(const float4*)p1;
            acc[0] += w0 * a.x + w1 * b.x;
            acc[1] += w0 * a.y + w1 * b.y;
            acc[2] += w0 * a.z + w1 * b.z;
            acc[3] += w0 * a.w + w1 * b.w;
        } else if constexpr (V == 2) {
            float2 a = *(const float2*)p0, b = *(const float2*)p1;
            acc[0] += w0 * a.x + w1 * b.x;
            acc[1] += w0 * a.y + w1 * b.y;
        } else {
            acc[0] += w0 * p0[0] + w1 * p1[0];
        }
    }
    if (j < r1) {
        int   s0 = __ldg(g_csr_src + j);
        float w0 = __ldg(g_csr_w + j);
        const float* p0 = in + (size_t)s0 * F + lane * V;
        if constexpr (V == 4) {
            float4 a = *(const float4*)p0;
            acc[0] += w0 * a.x; acc[1] += w0 * a.y;
            acc[2] += w0 * a.z; acc[3] += w0 * a.w;
        } else if constexpr (V == 2) {
            float2 a = *(const float2*)p0;
            acc[0] += w0 * a.x; acc[1] += w0 * a.y;
        } else {
            acc[0] += w0 * p0[0];
        }
    }

    float* q = out + (size_t)warp * F + lane * V;
    if constexpr (V == 4)      *(float4*)q = make_float4(acc[0], acc[1], acc[2], acc[3]);
    else if constexpr (V == 2) *(float2*)q = make_float2(acc[0], acc[1]);
    else                       q[0] = acc[0];
}

// ---------------- weight/BN prep -------------------------------------------
__global__ void k_prep(const float* __restrict__ W, const float* __restrict__ b,
                       const float* __restrict__ g, const float* __restrict__ be,
                       const float* __restrict__ m, const float* __restrict__ v,
                       int Fin, int Fout) {
    int tid = threadIdx.x;
    int tot = Fin * Fout;
    for (int i = tid; i < tot; i += blockDim.x) {
        float w0 = W[i], w1 = W[tot + i], w2 = W[2 * tot + i];
        g_Wc[i]           = w0 - w2;
        g_Wc[tot + i]     = w1;
        g_Wc[2 * tot + i] = 2.0f * w2;
    }
    if (tid < Fout) {
        float s = g[tid] * rsqrtf(v[tid] + 1e-5f);
        g_sc[tid] = s;
        g_sh[tid] = (b[tid] - m[tid]) * s + be[tid];
    }
}

// ---------------- fused 3-way GEMM + BN + LeakyReLU ------------------------
template <int BN, int FIN>
__global__ void __launch_bounds__(256) k_gemm(const float* __restrict__ A0,
                                              const float* __restrict__ P1,
                                              const float* __restrict__ P2,
                                              float* __restrict__ H) {
    constexpr int TN = BN / 16;
    __shared__ __align__(16) float As[64][20];
    __shared__ __align__(16) float Bs[16][BN];
    int t = threadIdx.x;
    int tx = t & 15, ty = t >> 4;
    int m0 = blockIdx.x * 64;

    float acc[4][TN];
#pragma unroll
    for (int i = 0; i < 4; i++)
#pragma unroll
        for (int j = 0; j < TN; j++) acc[i][j] = 0.0f;

    int lr = t >> 2;
    int lc = (t & 3) * 4;
    constexpr int BROW_T = BN / 4;
    int mg_l = m0 + lr;

    for (int k0 = 0; k0 < 3 * FIN; k0 += 16) {
        const float* src;
        int col0;
        if (k0 < FIN)            { src = A0; col0 = k0; }
        else if (k0 < 2 * FIN)   { src = P1; col0 = k0 - FIN; }
        else                     { src = P2; col0 = k0 - 2 * FIN; }

        float4 av = make_float4(0.f, 0.f, 0.f, 0.f);
        if (mg_l < NN) av = *(const float4*)(src + (size_t)mg_l * FIN + col0 + lc);
        *(float4*)&As[lr][lc] = av;

        if (t < 16 * BROW_T) {
            int brow = t / BROW_T;
            int bc4 = (t % BROW_T) * 4;
            *(float4*)&Bs[brow][bc4] = *(const float4*)(g_Wc + (k0 + brow) * BN + bc4);
        }
        __syncthreads();

#pragma unroll
        for (int kk = 0; kk < 16; kk++) {
            float a[4], bb[TN];
#pragma unroll
            for (int i = 0; i < 4; i++) a[i] = As[ty + 16 * i][kk];
#pragma unroll
            for (int j = 0; j < TN; j++) bb[j] = Bs[kk][tx + 16 * j];
#pragma unroll
            for (int i = 0; i < 4; i++)
#pragma unroll
                for (int j = 0; j < TN; j++) acc[i][j] += a[i] * bb[j];
        }
        __syncthreads();
    }

#pragma unroll
    for (int j = 0; j < TN; j++) {
        int n = tx + 16 * j;
        float s = g_sc[n], sh = g_sh[n];
#pragma unroll
        for (int i = 0; i < 4; i++) {
            int mg = m0 + ty + 16 * i;
            if (mg < NN) {
                float y = acc[i][j] * s + sh;
                H[(size_t)mg * BN + n] = y > 0.0f ? y : 0.01f * y;
            }
        }
    }
}

// ---------------- global mean pool ------------------------------------------
__global__ void k_pool(const float* __restrict__ H, const int* __restrict__ batch) {
    constexpr int CH = 16;
    int tid = blockIdx.x * blockDim.x + threadIdx.x;
    int n0 = tid * CH;
    if (n0 >= NN) return;
    int n1 = n0 + CH; if (n1 > NN) n1 = NN;

    float acc[16];
#pragma unroll
    for (int f = 0; f < 16; f++) acc[f] = 0.0f;
    float cnt = 0.0f;
    int cur = batch[n0];

    for (int n = n0; n < n1; n++) {
        int b = batch[n];
        if (b != cur) {
#pragma unroll
            for (int f = 0; f < 16; f++) atomicAdd(&g_pool[cur * 16 + f], acc[f]);
            atomicAdd(&g_pool[GG * 16 + cur], cnt);
#pragma unroll
            for (int f = 0; f < 16; f++) acc[f] = 0.0f;
            cnt = 0.0f;
            cur = b;
        }
        const float4* r = (const float4*)(H + (size_t)n * 16);
        float4 r0 = r[0], r1 = r[1], r2 = r[2], r3 = r[3];
        acc[0] += r0.x; acc[1] += r0.y; acc[2] += r0.z; acc[3] += r0.w;
        acc[4] += r1.x; acc[5] += r1.y; acc[6] += r1.z; acc[7] += r1.w;
        acc[8] += r2.x; acc[9] += r2.y; acc[10] += r2.z; acc[11] += r2.w;
        acc[12] += r3.x; acc[13] += r3.y; acc[14] += r3.z; acc[15] += r3.w;
        cnt += 1.0f;
    }
#pragma unroll
    for (int f = 0; f < 16; f++) atomicAdd(&g_pool[cur * 16 + f], acc[f]);
    atomicAdd(&g_pool[GG * 16 + cur], cnt);
}

// ---------------- final linear ----------------------------------------------
__global__ void k_final(const float* __restrict__ lw, const float* __restrict__ lb,
                        float* __restrict__ out) {
    int tid = threadIdx.x;
    if (tid >= GG * 2) return;
    int g = tid >> 1, o = tid & 1;
    float c = g_pool[GG * 16 + g];
    if (c < 1.0f) c = 1.0f;
    float inv = 1.0f / c;
    float s = 0.0f;
#pragma unroll
    for (int f = 0; f < 16; f++)
        s += g_pool[g * 16 + f] * inv * lw[o * 16 + f];
    out[tid] = s + lb[o];
}

// ---------------- host orchestration ---------------------------------------
extern "C" void kernel_launch(void* const* d_in, const int* in_sizes, int n_in,
                              void* d_out, int out_size) {
    (void)in_sizes; (void)n_in; (void)out_size;
    const float* x     = (const float*)d_in[0];
    const int*   ei    = (const int*)d_in[1];
    const int*   batch = (const int*)d_in[2];
    const float* W1 = (const float*)d_in[3],  *b1 = (const float*)d_in[4];
    const float* g1 = (const float*)d_in[5],  *be1 = (const float*)d_in[6];
    const float* m1 = (const float*)d_in[7],  *v1 = (const float*)d_in[8];
    const float* W2 = (const float*)d_in[9],  *b2 = (const float*)d_in[10];
    const float* g2 = (const float*)d_in[11], *be2 = (const float*)d_in[12];
    const float* m2 = (const float*)d_in[13], *v2 = (const float*)d_in[14];
    const float* W3 = (const float*)d_in[15], *b3 = (const float*)d_in[16];
    const float* g3 = (const float*)d_in[17], *be3 = (const float*)d_in[18];
    const float* m3 = (const float*)d_in[19], *v3 = (const float*)d_in[20];
    const float* lw = (const float*)d_in[21], *lb = (const float*)d_in[22];
    float* out = (float*)d_out;

    float *p_P1, *p_P2, *p_H1, *p_H2, *p_H3, *p_pool;
    int *p_degi, *p_cnt, *p_rowptr, *p_cursor;
    cudaGetSymbolAddress((void**)&p_degi,   g_degi);
    cudaGetSymbolAddress((void**)&p_cnt,    g_cnt);
    cudaGetSymbolAddress((void**)&p_rowptr, g_rowptr);
    cudaGetSymbolAddress((void**)&p_cursor, g_cursor);
    cudaGetSymbolAddress((void**)&p_P1,     g_P1);
    cudaGetSymbolAddress((void**)&p_P2,     g_P2);
    cudaGetSymbolAddress((void**)&p_H1,     g_H1);
    cudaGetSymbolAddress((void**)&p_H2,     g_H2);
    cudaGetSymbolAddress((void**)&p_H3,     g_H3);
    cudaGetSymbolAddress((void**)&p_pool,   g_pool);

    cudaMemsetAsync(p_degi, 0, NN * sizeof(int));
    cudaMemsetAsync(p_cnt,  0, NN * sizeof(int));
    cudaMemsetAsync(p_pool, 0, (GG * 16 + GG) * sizeof(float));

    int eb = (EE + 255) / 256;

    // ----- CSR build (shared by all 6 props) -----
    k_degcnt<<<eb, 256>>>(ei);
    k_scan1<<<NBLK, SCAN_BLK>>>();
    k_scan2<<<1, 256>>>();
    k_scan3<<<(NN + 255) / 256, 256>>>();
    cudaMemcpyAsync(p_cursor, p_rowptr, NN * sizeof(int), cudaMemcpyDeviceToDevice);
    k_fill<<<eb, 256>>>(ei);

    int gwarp = ((NN * 32) + 255) / 256;   // warp per node

    // ----- layer 1: 128 -> 64 -----
    k_prep<<<1, 256>>>(W1, b1, g1, be1, m1, v1, 128, 64);
    k_gather<128><<<gwarp, 256>>>(x,    p_P1);
    k_gather<128><<<gwarp, 256>>>(p_P1, p_P2);
    k_gemm<64, 128><<<(NN + 63) / 64, 256>>>(x, p_P1, p_P2, p_H1);

    // ----- layer 2: 64 -> 32 -----
    k_prep<<<1, 256>>>(W2, b2, g2, be2, m2, v2, 64, 32);
    k_gather<64><<<gwarp, 256>>>(p_H1, p_P1);
    k_gather<64><<<gwarp, 256>>>(p_P1, p_P2);
    k_gemm<32, 64><<<(NN + 63) / 64, 256>>>(p_H1, p_P1, p_P2, p_H2);

    // ----- layer 3: 32 -> 16 -----
    k_prep<<<1, 256>>>(W3, b3, g3, be3, m3, v3, 32, 16);
    k_gather<32><<<gwarp, 256>>>(p_H2, p_P1);
    k_gather<32><<<gwarp, 256>>>(p_P1, p_P2);
    k_gemm<16, 32><<<(NN + 63) / 64, 256>>>(p_H2, p_P1, p_P2, p_H3);

    // ----- pool + classifier -----
    {
        int threads = (NN + 15) / 16;
        int gb = (threads + 255) / 256;
        k_pool<<<gb, 256>>>(p_H3, batch);
    }
    k_final<<<1, 128>>>(lw, lb, out);
}

// round 9
// speedup vs baseline: 1.5235x; 1.0827x over previous
#include <cuda_runtime.h>
#include <cstdint>

#define NN 100000
#define EE 640000
#define GG 64
#define SCAN_BLK 512
#define NBLK ((NN + SCAN_BLK - 1) / SCAN_BLK)   // 196

// ---------------- scratch ---------------------------------------------------
__device__ __align__(16) int   g_degi[NN];
__device__ __align__(16) int   g_cnt[NN];
__device__ __align__(16) int   g_incl[NN];
__device__ __align__(16) int   g_bsum[NBLK];
__device__ __align__(16) int   g_rowptr[NN + 1];
__device__ __align__(16) int   g_cursor[NN];
__device__ __align__(16) int   g_csr_src[EE];
__device__ __align__(16) float g_csr_w[EE];
__device__ __align__(16) float g_Y0[NN * 64];    // projected order-0 term
__device__ __align__(16) float g_YP[NN * 128];   // [Y1|Y2] per row
__device__ __align__(16) float g_U[NN * 128];    // [P(Y1)|P(Y2)]
__device__ __align__(16) float g_H1[NN * 64];
__device__ __align__(16) float g_H2[NN * 32];
__device__ __align__(16) float g_H3[NN * 16];
__device__ __align__(16) float g_Wc[128 * 192];  // padded combined weights
__device__ __align__(16) float g_sc[64];
__device__ __align__(16) float g_sh[64];
__device__ __align__(16) float g_pool[GG * 16 + GG];

// ---------------- CSR build -------------------------------------------------
__global__ void k_degcnt(const int* __restrict__ ei) {
    int e = blockIdx.x * blockDim.x + threadIdx.x;
    if (e >= EE) return;
    int s = ei[e], d = ei[EE + e];
    if (s != d) {
        atomicAdd(&g_degi[s], 1);
        atomicAdd(&g_cnt[d], 1);
    }
}

__global__ void k_scan1() {
    __shared__ int sh[SCAN_BLK];
    int i = blockIdx.x * SCAN_BLK + threadIdx.x;
    int v = (i < NN) ? g_cnt[i] : 0;
    sh[threadIdx.x] = v;
    __syncthreads();
#pragma unroll
    for (int off = 1; off < SCAN_BLK; off <<= 1) {
        int t = (threadIdx.x >= off) ? sh[threadIdx.x - off] : 0;
        __syncthreads();
        sh[threadIdx.x] += t;
        __syncthreads();
    }
    if (i < NN) g_incl[i] = sh[threadIdx.x];
    if (threadIdx.x == SCAN_BLK - 1) g_bsum[blockIdx.x] = sh[threadIdx.x];
}

__global__ void k_scan2() {
    __shared__ int sh[256];
    int t = threadIdx.x;
    int v = (t < NBLK) ? g_bsum[t] : 0;
    sh[t] = v;
    __syncthreads();
#pragma unroll
    for (int off = 1; off < 256; off <<= 1) {
        int u = (t >= off) ? sh[t - off] : 0;
        __syncthreads();
        sh[t] += u;
        __syncthreads();
    }
    if (t < NBLK) g_bsum[t] = (t > 0) ? sh[t - 1] : 0;   // exclusive
}

__global__ void k_scan3() {
    int i = blockIdx.x * blockDim.x + threadIdx.x;
    if (i < NN) g_rowptr[i + 1] = g_incl[i] + g_bsum[i / SCAN_BLK];
    if (i == 0) g_rowptr[0] = 0;
}

__global__ void k_fill(const int* __restrict__ ei) {
    int e = blockIdx.x * blockDim.x + threadIdx.x;
    if (e >= EE) return;
    int s = ei[e], d = ei[EE + e];
    if (s == d) return;
    float is = rsqrtf((float)g_degi[s]);          // >= 1 (this edge counts)
    int dd = g_degi[d];
    float id = dd > 0 ? rsqrtf((float)dd) : 0.0f;
    float w = -is * id;
    int pos = atomicAdd(&g_cursor[d], 1);
    g_csr_src[pos] = s;
    g_csr_w[pos] = w;
}

// ---------------- weight/BN prep: fold Cheb + BN, pad to BNP ---------------
__global__ void k_prep(const float* __restrict__ W, const float* __restrict__ b,
                       const float* __restrict__ g, const float* __restrict__ be,
                       const float* __restrict__ m, const float* __restrict__ v,
                       int Fin, int Fout, int BNP) {
    int tid = threadIdx.x;
    int tot = Fin * Fout;
    for (int i = tid; i < Fin * BNP; i += blockDim.x) {
        int k = i / BNP, c = i % BNP;
        float val = 0.0f;
        if (c < Fout)          val = W[k * Fout + c] - W[2 * tot + k * Fout + c];
        else if (c < 2 * Fout) val = W[tot + k * Fout + (c - Fout)];
        else if (c < 3 * Fout) val = 2.0f * W[2 * tot + k * Fout + (c - 2 * Fout)];
        g_Wc[i] = val;
    }
    if (tid < Fout) {
        float s = g[tid] * rsqrtf(v[tid] + 1e-5f);
        g_sc[tid] = s;
        g_sh[tid] = (b[tid] - m[tid]) * s + be[tid];
    }
}

// ---------------- packed f32x2 GEMM: [Y0|YP] = A @ Wc ----------------------
__device__ __forceinline__ void fma2(unsigned long long& d,
                                     unsigned long long a, unsigned long long b) {
    asm("fma.rn.f32x2 %0, %1, %2, %0;" : "+l"(d) : "l"(a), "l"(b));
}

template <int FIN, int FOUT, int BNP, int CW>
__global__ void __launch_bounds__(256) k_gemmY(const float* __restrict__ A,
                                               float* __restrict__ Y0,
                                               float* __restrict__ YP) {
    constexpr int NP = BNP / 32;          // u64 accumulators per row per thread
    constexpr int NC = BNP / (16 * CW);   // column chunks (CW cols each)
    __shared__ __align__(16) float As[64][20];
    __shared__ __align__(16) float Bs[16][BNP];
    int t = threadIdx.x;
    int tx = t & 15, ty = t >> 4;
    int m0 = blockIdx.x * 64;

    unsigned long long acc[4][NP];
#pragma unroll
    for (int i = 0; i < 4; i++)
#pragma unroll
        for (int p = 0; p < NP; p++) acc[i][p] = 0ULL;

    int lr = t >> 2, lc = (t & 3) * 4;
    int mg_l = m0 + lr;

    for (int k0 = 0; k0 < FIN; k0 += 16) {
        float4 av = make_float4(0.f, 0.f, 0.f, 0.f);
        if (mg_l < NN) av = *(const float4*)(A + (size_t)mg_l * FIN + k0 + lc);
        *(float4*)&As[lr][lc] = av;
#pragma unroll
        for (int idx = t; idx < 16 * BNP / 4; idx += 256) {
            int br = idx / (BNP / 4), bc = (idx % (BNP / 4)) * 4;
            *(float4*)&Bs[br][bc] = *(const float4*)(g_Wc + (k0 + br) * BNP + bc);
        }
        __syncthreads();

#pragma unroll
        for (int kk = 0; kk < 16; kk++) {
            unsigned long long a2[4];
#pragma unroll
            for (int i = 0; i < 4; i++) {
                unsigned int au = __float_as_uint(As[ty + 16 * i][kk]);
                asm("mov.b64 %0, {%1,%1};" : "=l"(a2[i]) : "r"(au));
            }
            unsigned long long b2[NP];
            if (CW == 4) {
#pragma unroll
                for (int ch = 0; ch < NC; ch++) {
                    ulonglong2 bb = *(const ulonglong2*)&Bs[kk][4 * tx + 64 * ch];
                    b2[2 * ch] = bb.x; b2[2 * ch + 1] = bb.y;
                }
            } else {
#pragma unroll
                for (int p = 0; p < NP; p++)
                    b2[p] = *(const unsigned long long*)&Bs[kk][2 * tx + 32 * p];
            }
#pragma unroll
            for (int i = 0; i < 4; i++)
#pragma unroll
                for (int p = 0; p < NP; p++) fma2(acc[i][p], a2[i], b2[p]);
        }
        __syncthreads();
    }

#pragma unroll
    for (int i = 0; i < 4; i++) {
        int row = m0 + ty + 16 * i;
        if (row >= NN) continue;
#pragma unroll
        for (int p = 0; p < NP; p++) {
            int c = (CW == 4) ? (4 * tx + 64 * (p >> 1) + 2 * (p & 1))
                              : (2 * tx + 32 * p);
            if (c >= 3 * FOUT) continue;   // pad columns (layer 3)
            union { unsigned long long u; float2 f; } cv; cv.u = acc[i][p];
            if (c < FOUT) *(float2*)(Y0 + (size_t)row * FOUT + c) = cv.f;
            else          *(float2*)(YP + (size_t)row * 2 * FOUT + (c - FOUT)) = cv.f;
        }
    }
}

// ---------------- plain gather: out = P(in), width F ------------------------
template <int F>
__global__ void __launch_bounds__(256) k_gather(const float* __restrict__ in,
                                                float* __restrict__ out) {
    int warp = (blockIdx.x * blockDim.x + threadIdx.x) >> 5;
    int lane = threadIdx.x & 31;
    if (warp >= NN) return;
    int r0 = g_rowptr[warp], r1 = g_rowptr[warp + 1];
    constexpr int V = F / 32;
    float acc[V];
#pragma unroll
    for (int i = 0; i < V; i++) acc[i] = 0.0f;

    int j = r0;
    for (; j + 1 < r1; j += 2) {
        int   s0 = __ldg(g_csr_src + j), s1 = __ldg(g_csr_src + j + 1);
        float w0 = __ldg(g_csr_w + j),   w1 = __ldg(g_csr_w + j + 1);
        const float* p0 = in + (size_t)s0 * F + lane * V;
        const float* p1 = in + (size_t)s1 * F + lane * V;
        if constexpr (V == 4) {
            float4 a = *(const float4*)p0, b = *(const float4*)p1;
            acc[0] += w0 * a.x + w1 * b.x;
            acc[1] += w0 * a.y + w1 * b.y;
            acc[2] += w0 * a.z + w1 * b.z;
            acc[3] += w0 * a.w + w1 * b.w;
        } else if constexpr (V == 2) {
            float2 a = *(const float2*)p0, b = *(const float2*)p1;
            acc[0] += w0 * a.x + w1 * b.x;
            acc[1] += w0 * a.y + w1 * b.y;
        } else {
            acc[0] += w0 * p0[0] + w1 * p1[0];
        }
    }
    if (j < r1) {
        int   s0 = __ldg(g_csr_src + j);
        float w0 = __ldg(g_csr_w + j);
        const float* p0 = in + (size_t)s0 * F + lane * V;
        if constexpr (V == 4) {
            float4 a = *(const float4*)p0;
            acc[0] += w0 * a.x; acc[1] += w0 * a.y;
            acc[2] += w0 * a.z; acc[3] += w0 * a.w;
        } else if constexpr (V == 2) {
            float2 a = *(const float2*)p0;
            acc[0] += w0 * a.x; acc[1] += w0 * a.y;
        } else {
            acc[0] += w0 * p0[0];
        }
    }

    float* q = out + (size_t)warp * F + lane * V;
    if constexpr (V == 4)      *(float4*)q = make_float4(acc[0], acc[1], acc[2], acc[3]);
    else if constexpr (V == 2) *(float2*)q = make_float2(acc[0], acc[1]);
    else                       q[0] = acc[0];
}

// ------- fused gather + epilogue: H = leaky(bn(Y0 + U[:,:F] + P(U[:,F:]))) -
template <int F, int V>
__global__ void __launch_bounds__(256) k_gepi(const float* __restrict__ U,
                                              const float* __restrict__ Y0,
                                              float* __restrict__ H) {
    constexpr int TPN = F / V;
    int gid = blockIdx.x * blockDim.x + threadIdx.x;
    int node = gid / TPN;
    if (node >= NN) return;
    int col = (gid % TPN) * V;
    int r0 = g_rowptr[node], r1 = g_rowptr[node + 1];
    float acc[V];
#pragma unroll
    for (int v = 0; v < V; v++) acc[v] = 0.0f;

    const float* Us = U + F + col;   // second half of U rows
    int j = r0;
    for (; j + 1 < r1; j += 2) {
        int   s0 = __ldg(g_csr_src + j), s1 = __ldg(g_csr_src + j + 1);
        float w0 = __ldg(g_csr_w + j),   w1 = __ldg(g_csr_w + j + 1);
        if constexpr (V == 2) {
            float2 a = *(const float2*)(Us + (size_t)s0 * 2 * F);
            float2 b = *(const float2*)(Us + (size_t)s1 * 2 * F);
            acc[0] += w0 * a.x + w1 * b.x;
            acc[1] += w0 * a.y + w1 * b.y;
        } else {
            acc[0] += w0 * Us[(size_t)s0 * 2 * F] + w1 * Us[(size_t)s1 * 2 * F];
        }
    }
    if (j < r1) {
        int   s0 = __ldg(g_csr_src + j);
        float w0 = __ldg(g_csr_w + j);
        if constexpr (V == 2) {
            float2 a = *(const float2*)(Us + (size_t)s0 * 2 * F);
            acc[0] += w0 * a.x; acc[1] += w0 * a.y;
        } else {
            acc[0] += w0 * Us[(size_t)s0 * 2 * F];
        }
    }

#pragma unroll
    for (int v = 0; v < V; v++) {
        float y = Y0[(size_t)node * F + col + v]
                + U[(size_t)node * 2 * F + col + v] + acc[v];
        y = y * g_sc[col + v] + g_sh[col + v];
        H[(size_t)node * F + col + v] = y > 0.0f ? y : 0.01f * y;
    }
}

// ---------------- global mean pool ------------------------------------------
__global__ void k_pool(const float* __restrict__ H, const int* __restrict__ batch) {
    constexpr int CH = 16;
    int tid = blockIdx.x * blockDim.x + threadIdx.x;
    int n0 = tid * CH;
    if (n0 >= NN) return;
    int n1 = n0 + CH; if (n1 > NN) n1 = NN;

    float acc[16];
#pragma unroll
    for (int f = 0; f < 16; f++) acc[f] = 0.0f;
    float cnt = 0.0f;
    int cur = batch[n0];

    for (int n = n0; n < n1; n++) {
        int b = batch[n];
        if (b != cur) {
#pragma unroll
            for (int f = 0; f < 16; f++) atomicAdd(&g_pool[cur * 16 + f], acc[f]);
            atomicAdd(&g_pool[GG * 16 + cur], cnt);
#pragma unroll
            for (int f = 0; f < 16; f++) acc[f] = 0.0f;
            cnt = 0.0f;
            cur = b;
        }
        const float4* r = (const float4*)(H + (size_t)n * 16);
        float4 r0 = r[0], r1 = r[1], r2 = r[2], r3 = r[3];
        acc[0] += r0.x; acc[1] += r0.y; acc[2] += r0.z; acc[3] += r0.w;
        acc[4] += r1.x; acc[5] += r1.y; acc[6] += r1.z; acc[7] += r1.w;
        acc[8] += r2.x; acc[9] += r2.y; acc[10] += r2.z; acc[11] += r2.w;
        acc[12] += r3.x; acc[13] += r3.y; acc[14] += r3.z; acc[15] += r3.w;
        cnt += 1.0f;
    }
#pragma unroll
    for (int f = 0; f < 16; f++) atomicAdd(&g_pool[cur * 16 + f], acc[f]);
    atomicAdd(&g_pool[GG * 16 + cur], cnt);
}

// ---------------- final linear ----------------------------------------------
__global__ void k_final(const float* __restrict__ lw, const float* __restrict__ lb,
                        float* __restrict__ out) {
    int tid = threadIdx.x;
    if (tid >= GG * 2) return;
    int g = tid >> 1, o = tid & 1;
    float c = g_pool[GG * 16 + g];
    if (c < 1.0f) c = 1.0f;
    float inv = 1.0f / c;
    float s = 0.0f;
#pragma unroll
    for (int f = 0; f < 16; f++)
        s += g_pool[g * 16 + f] * inv * lw[o * 16 + f];
    out[tid] = s + lb[o];
}

// ---------------- host orchestration ---------------------------------------
extern "C" void kernel_launch(void* const* d_in, const int* in_sizes, int n_in,
                              void* d_out, int out_size) {
    (void)in_sizes; (void)n_in; (void)out_size;
    const float* x     = (const float*)d_in[0];
    const int*   ei    = (const int*)d_in[1];
    const int*   batch = (const int*)d_in[2];
    const float* W1 = (const float*)d_in[3],  *b1 = (const float*)d_in[4];
    const float* g1 = (const float*)d_in[5],  *be1 = (const float*)d_in[6];
    const float* m1 = (const float*)d_in[7],  *v1 = (const float*)d_in[8];
    const float* W2 = (const float*)d_in[9],  *b2 = (const float*)d_in[10];
    const float* g2 = (const float*)d_in[11], *be2 = (const float*)d_in[12];
    const float* m2 = (const float*)d_in[13], *v2 = (const float*)d_in[14];
    const float* W3 = (const float*)d_in[15], *b3 = (const float*)d_in[16];
    const float* g3 = (const float*)d_in[17], *be3 = (const float*)d_in[18];
    const float* m3 = (const float*)d_in[19], *v3 = (const float*)d_in[20];
    const float* lw = (const float*)d_in[21], *lb = (const float*)d_in[22];
    float* out = (float*)d_out;

    float *p_Y0, *p_YP, *p_U, *p_H1, *p_H2, *p_H3, *p_pool;
    int *p_degi, *p_cnt, *p_rowptr, *p_cursor;
    cudaGetSymbolAddress((void**)&p_degi,   g_degi);
    cudaGetSymbolAddress((void**)&p_cnt,    g_cnt);
    cudaGetSymbolAddress((void**)&p_rowptr, g_rowptr);
    cudaGetSymbolAddress((void**)&p_cursor, g_cursor);
    cudaGetSymbolAddress((void**)&p_Y0,     g_Y0);
    cudaGetSymbolAddress((void**)&p_YP,     g_YP);
    cudaGetSymbolAddress((void**)&p_U,      g_U);
    cudaGetSymbolAddress((void**)&p_H1,     g_H1);
    cudaGetSymbolAddress((void**)&p_H2,     g_H2);
    cudaGetSymbolAddress((void**)&p_H3,     g_H3);
    cudaGetSymbolAddress((void**)&p_pool,   g_pool);

    cudaMemsetAsync(p_degi, 0, NN * sizeof(int));
    cudaMemsetAsync(p_cnt,  0, NN * sizeof(int));
    cudaMemsetAsync(p_pool, 0, (GG * 16 + GG) * sizeof(float));

    int eb = (EE + 255) / 256;

    // ----- CSR build (shared by all props) -----
    k_degcnt<<<eb, 256>>>(ei);
    k_scan1<<<NBLK, SCAN_BLK>>>();
    k_scan2<<<1, 256>>>();
    k_scan3<<<(NN + 255) / 256, 256>>>();
    cudaMemcpyAsync(p_cursor, p_rowptr, NN * sizeof(int), cudaMemcpyDeviceToDevice);
    k_fill<<<eb, 256>>>(ei);

    int gm = (NN + 63) / 64;                 // GEMM blocks
    int gw32 = ((NN * 32) + 255) / 256;      // 32 threads/node
    int gw16 = ((NN * 16) + 255) / 256;      // 16 threads/node

    // ----- layer 1: 128 -> 64 -----
    k_prep<<<1, 256>>>(W1, b1, g1, be1, m1, v1, 128, 64, 192);
    k_gemmY<128, 64, 192, 4><<<gm, 256>>>(x, p_Y0, p_YP);
    k_gather<128><<<gw32, 256>>>(p_YP, p_U);
    k_gepi<64, 2><<<gw32, 256>>>(p_U, p_Y0, p_H1);

    // ----- layer 2: 64 -> 32 -----
    k_prep<<<1, 256>>>(W2, b2, g2, be2, m2, v2, 64, 32, 96);
    k_gemmY<64, 32, 96, 2><<<gm, 256>>>(p_H1, p_Y0, p_YP);
    k_gather<64><<<gw32, 256>>>(p_YP, p_U);
    k_gepi<32, 1><<<gw32, 256>>>(p_U, p_Y0, p_H2);

    // ----- layer 3: 32 -> 16 -----
    k_prep<<<1, 256>>>(W3, b3, g3, be3, m3, v3, 32, 16, 64);
    k_gemmY<32, 16, 64, 4><<<gm, 256>>>(p_H2, p_Y0, p_YP);
    k_gather<32><<<gw32, 256>>>(p_YP, p_U);
    k_gepi<16, 1><<<gw16, 256>>>(p_U, p_Y0, p_H3);

    // ----- pool + classifier -----
    {
        int threads = (NN + 15) / 16;
        int gb = (threads + 255) / 256;
        k_pool<<<gb, 256>>>(p_H3, batch);
    }
    k_final<<<1, 128>>>(lw, lb, out);
}

// round 10
// speedup vs baseline: 1.5827x; 1.0389x over previous
#include <cuda_runtime.h>
#include <cstdint>

#define NN 100000
#define EE 640000
#define GG 64
#define SCAN_BLK 512
#define NBLK ((NN + SCAN_BLK - 1) / SCAN_BLK)   // 196

// ---------------- scratch ---------------------------------------------------
__device__ __align__(16) int   g_degi[NN];
__device__ __align__(16) int   g_cnt[NN];
__device__ __align__(16) int   g_incl[NN];
__device__ __align__(16) int   g_bsum[NBLK];
__device__ __align__(16) int   g_rowptr[NN + 1];
__device__ __align__(16) int   g_cursor[NN];
__device__ __align__(16) int   g_csr_src[EE];
__device__ __align__(16) float g_csr_w[EE];
__device__ __align__(16) float g_Y0[NN * 64];    // order-0 projected term
__device__ __align__(16) float g_Y1[NN * 64];    // order-1 projected term
__device__ __align__(16) float g_Y2[NN * 64];    // order-2 projected term (x2)
__device__ __align__(16) float g_Z[NN * 64];     // Z = Y1 + P(Y2)
__device__ __align__(16) float g_H1[NN * 64];
__device__ __align__(16) float g_H2[NN * 32];
__device__ __align__(16) float g_H3[NN * 16];
__device__ __align__(16) float g_Wc[128 * 192];  // padded combined weights
__device__ __align__(16) float g_sc[64];
__device__ __align__(16) float g_sh[64];
__device__ __align__(16) float g_pool[GG * 16 + GG];

// ---------------- CSR build -------------------------------------------------
__global__ void k_degcnt(const int* __restrict__ ei) {
    int e = blockIdx.x * blockDim.x + threadIdx.x;
    if (e >= EE) return;
    int s = ei[e], d = ei[EE + e];
    if (s != d) {
        atomicAdd(&g_degi[s], 1);
        atomicAdd(&g_cnt[d], 1);
    }
}

__global__ void k_scan1() {
    __shared__ int sh[SCAN_BLK];
    int i = blockIdx.x * SCAN_BLK + threadIdx.x;
    int v = (i < NN) ? g_cnt[i] : 0;
    sh[threadIdx.x] = v;
    __syncthreads();
#pragma unroll
    for (int off = 1; off < SCAN_BLK; off <<= 1) {
        int t = (threadIdx.x >= off) ? sh[threadIdx.x - off] : 0;
        __syncthreads();
        sh[threadIdx.x] += t;
        __syncthreads();
    }
    if (i < NN) g_incl[i] = sh[threadIdx.x];
    if (threadIdx.x == SCAN_BLK - 1) g_bsum[blockIdx.x] = sh[threadIdx.x];
}

__global__ void k_scan2() {
    __shared__ int sh[256];
    int t = threadIdx.x;
    int v = (t < NBLK) ? g_bsum[t] : 0;
    sh[t] = v;
    __syncthreads();
#pragma unroll
    for (int off = 1; off < 256; off <<= 1) {
        int u = (t >= off) ? sh[t - off] : 0;
        __syncthreads();
        sh[t] += u;
        __syncthreads();
    }
    if (t < NBLK) g_bsum[t] = (t > 0) ? sh[t - 1] : 0;   // exclusive
}

__global__ void k_scan3() {
    int i = blockIdx.x * blockDim.x + threadIdx.x;
    if (i < NN) g_rowptr[i + 1] = g_incl[i] + g_bsum[i / SCAN_BLK];
    if (i == 0) g_rowptr[0] = 0;
}

__global__ void k_fill(const int* __restrict__ ei) {
    int e = blockIdx.x * blockDim.x + threadIdx.x;
    if (e >= EE) return;
    int s = ei[e], d = ei[EE + e];
    if (s == d) return;
    float is = rsqrtf((float)g_degi[s]);          // >= 1 (this edge counts)
    int dd = g_degi[d];
    float id = dd > 0 ? rsqrtf((float)dd) : 0.0f;
    float w = -is * id;
    int pos = atomicAdd(&g_cursor[d], 1);
    g_csr_src[pos] = s;
    g_csr_w[pos] = w;
}

// ---------------- weight/BN prep: fold Cheb + BN, pad to BNP ---------------
__global__ void k_prep(const float* __restrict__ W, const float* __restrict__ b,
                       const float* __restrict__ g, const float* __restrict__ be,
                       const float* __restrict__ m, const float* __restrict__ v,
                       int Fin, int Fout, int BNP) {
    int tid = threadIdx.x;
    int tot = Fin * Fout;
    for (int i = tid; i < Fin * BNP; i += blockDim.x) {
        int k = i / BNP, c = i % BNP;
        float val = 0.0f;
        if (c < Fout)          val = W[k * Fout + c] - W[2 * tot + k * Fout + c];
        else if (c < 2 * Fout) val = W[tot + k * Fout + (c - Fout)];
        else if (c < 3 * Fout) val = 2.0f * W[2 * tot + k * Fout + (c - 2 * Fout)];
        g_Wc[i] = val;
    }
    if (tid < Fout) {
        float s = g[tid] * rsqrtf(v[tid] + 1e-5f);
        g_sc[tid] = s;
        g_sh[tid] = (b[tid] - m[tid]) * s + be[tid];
    }
}

// ---------------- packed f32x2 GEMM: [Y0|Y1|Y2] = A @ Wc -------------------
__device__ __forceinline__ void fma2(unsigned long long& d,
                                     unsigned long long a, unsigned long long b) {
    asm("fma.rn.f32x2 %0, %1, %2, %0;" : "+l"(d) : "l"(a), "l"(b));
}

template <int FIN, int FOUT, int BNP, int CW>
__global__ void __launch_bounds__(256) k_gemmY(const float* __restrict__ A,
                                               float* __restrict__ Y0,
                                               float* __restrict__ Y1,
                                               float* __restrict__ Y2) {
    constexpr int NP = BNP / 32;          // u64 accumulators per row per thread
    constexpr int NC = BNP / (16 * CW);   // column chunks (CW cols each)
    __shared__ __align__(16) float As[64][20];
    __shared__ __align__(16) float Bs[16][BNP];
    int t = threadIdx.x;
    int tx = t & 15, ty = t >> 4;
    int m0 = blockIdx.x * 64;

    unsigned long long acc[4][NP];
#pragma unroll
    for (int i = 0; i < 4; i++)
#pragma unroll
        for (int p = 0; p < NP; p++) acc[i][p] = 0ULL;

    int lr = t >> 2, lc = (t & 3) * 4;
    int mg_l = m0 + lr;

    for (int k0 = 0; k0 < FIN; k0 += 16) {
        float4 av = make_float4(0.f, 0.f, 0.f, 0.f);
        if (mg_l < NN) av = *(const float4*)(A + (size_t)mg_l * FIN + k0 + lc);
        *(float4*)&As[lr][lc] = av;
#pragma unroll
        for (int idx = t; idx < 16 * BNP / 4; idx += 256) {
            int br = idx / (BNP / 4), bc = (idx % (BNP / 4)) * 4;
            *(float4*)&Bs[br][bc] = *(const float4*)(g_Wc + (k0 + br) * BNP + bc);
        }
        __syncthreads();

#pragma unroll
        for (int kk = 0; kk < 16; kk++) {
            unsigned long long a2[4];
#pragma unroll
            for (int i = 0; i < 4; i++) {
                unsigned int au = __float_as_uint(As[ty + 16 * i][kk]);
                asm("mov.b64 %0, {%1,%1};" : "=l"(a2[i]) : "r"(au));
            }
            unsigned long long b2[NP];
            if (CW == 4) {
#pragma unroll
                for (int ch = 0; ch < NC; ch++) {
                    ulonglong2 bb = *(const ulonglong2*)&Bs[kk][4 * tx + 64 * ch];
                    b2[2 * ch] = bb.x; b2[2 * ch + 1] = bb.y;
                }
            } else {
#pragma unroll
                for (int p = 0; p < NP; p++)
                    b2[p] = *(const unsigned long long*)&Bs[kk][2 * tx + 32 * p];
            }
#pragma unroll
            for (int i = 0; i < 4; i++)
#pragma unroll
                for (int p = 0; p < NP; p++) fma2(acc[i][p], a2[i], b2[p]);
        }
        __syncthreads();
    }

#pragma unroll
    for (int i = 0; i < 4; i++) {
        int row = m0 + ty + 16 * i;
        if (row >= NN) continue;
#pragma unroll
        for (int p = 0; p < NP; p++) {
            int c = (CW == 4) ? (4 * tx + 64 * (p >> 1) + 2 * (p & 1))
                              : (2 * tx + 32 * p);
            if (c >= 3 * FOUT) continue;   // pad columns (layer 3)
            union { unsigned long long u; float2 f; } cv; cv.u = acc[i][p];
            if (c < FOUT)
                *(float2*)(Y0 + (size_t)row * FOUT + c) = cv.f;
            else if (c < 2 * FOUT)
                *(float2*)(Y1 + (size_t)row * FOUT + (c - FOUT)) = cv.f;
            else
                *(float2*)(Y2 + (size_t)row * FOUT + (c - 2 * FOUT)) = cv.f;
        }
    }
}

// ------- unified gather: O[i] = B[i] + P(S)[i]   (+BN+leaky if EPI) --------
template <int F, int TPN, bool EPI>
__global__ void __launch_bounds__(256) k_gath(const float* __restrict__ S,
                                              const float* __restrict__ B,
                                              float* __restrict__ O) {
    constexpr int V = F / TPN;
    int gid = blockIdx.x * blockDim.x + threadIdx.x;
    int node = gid / TPN;
    if (node >= NN) return;
    int col = (gid % TPN) * V;
    int r0 = g_rowptr[node], r1 = g_rowptr[node + 1];
    float acc[V];
#pragma unroll
    for (int v = 0; v < V; v++) acc[v] = 0.0f;

    const float* Sc = S + col;
    int j = r0;
    for (; j + 1 < r1; j += 2) {
        int   s0 = __ldg(g_csr_src + j), s1 = __ldg(g_csr_src + j + 1);
        float w0 = __ldg(g_csr_w + j),   w1 = __ldg(g_csr_w + j + 1);
        const float* p0 = Sc + (size_t)s0 * F;
        const float* p1 = Sc + (size_t)s1 * F;
        if constexpr (V == 2) {
            float2 a = *(const float2*)p0, b = *(const float2*)p1;
            acc[0] += w0 * a.x + w1 * b.x;
            acc[1] += w0 * a.y + w1 * b.y;
        } else {
            acc[0] += w0 * p0[0] + w1 * p1[0];
        }
    }
    if (j < r1) {
        int   s0 = __ldg(g_csr_src + j);
        float w0 = __ldg(g_csr_w + j);
        const float* p0 = Sc + (size_t)s0 * F;
        if constexpr (V == 2) {
            float2 a = *(const float2*)p0;
            acc[0] += w0 * a.x; acc[1] += w0 * a.y;
        } else {
            acc[0] += w0 * p0[0];
        }
    }

#pragma unroll
    for (int v = 0; v < V; v++) {
        float y = B[(size_t)node * F + col + v] + acc[v];
        if constexpr (EPI) {
            y = y * g_sc[col + v] + g_sh[col + v];
            y = y > 0.0f ? y : 0.01f * y;
        }
        O[(size_t)node * F + col + v] = y;
    }
}

// ---------------- global mean pool ------------------------------------------
__global__ void k_pool(const float* __restrict__ H, const int* __restrict__ batch) {
    constexpr int CH = 16;
    int tid = blockIdx.x * blockDim.x + threadIdx.x;
    int n0 = tid * CH;
    if (n0 >= NN) return;
    int n1 = n0 + CH; if (n1 > NN) n1 = NN;

    float acc[16];
#pragma unroll
    for (int f = 0; f < 16; f++) acc[f] = 0.0f;
    float cnt = 0.0f;
    int cur = batch[n0];

    for (int n = n0; n < n1; n++) {
        int b = batch[n];
        if (b != cur) {
#pragma unroll
            for (int f = 0; f < 16; f++) atomicAdd(&g_pool[cur * 16 + f], acc[f]);
            atomicAdd(&g_pool[GG * 16 + cur], cnt);
#pragma unroll
            for (int f = 0; f < 16; f++) acc[f] = 0.0f;
            cnt = 0.0f;
            cur = b;
        }
        const float4* r = (const float4*)(H + (size_t)n * 16);
        float4 r0 = r[0], r1 = r[1], r2 = r[2], r3 = r[3];
        acc[0] += r0.x; acc[1] += r0.y; acc[2] += r0.z; acc[3] += r0.w;
        acc[4] += r1.x; acc[5] += r1.y; acc[6] += r1.z; acc[7] += r1.w;
        acc[8] += r2.x; acc[9] += r2.y; acc[10] += r2.z; acc[11] += r2.w;
        acc[12] += r3.x; acc[13] += r3.y; acc[14] += r3.z; acc[15] += r3.w;
        cnt += 1.0f;
    }
#pragma unroll
    for (int f = 0; f < 16; f++) atomicAdd(&g_pool[cur * 16 + f], acc[f]);
    atomicAdd(&g_pool[GG * 16 + cur], cnt);
}

// ---------------- final linear ----------------------------------------------
__global__ void k_final(const float* __restrict__ lw, const float* __restrict__ lb,
                        float* __restrict__ out) {
    int tid = threadIdx.x;
    if (tid >= GG * 2) return;
    int g = tid >> 1, o = tid & 1;
    float c = g_pool[GG * 16 + g];
    if (c < 1.0f) c = 1.0f;
    float inv = 1.0f / c;
    float s = 0.0f;
#pragma unroll
    for (int f = 0; f < 16; f++)
        s += g_pool[g * 16 + f] * inv * lw[o * 16 + f];
    out[tid] = s + lb[o];
}

// ---------------- host orchestration ---------------------------------------
extern "C" void kernel_launch(void* const* d_in, const int* in_sizes, int n_in,
                              void* d_out, int out_size) {
    (void)in_sizes; (void)n_in; (void)out_size;
    const float* x     = (const float*)d_in[0];
    const int*   ei    = (const int*)d_in[1];
    const int*   batch = (const int*)d_in[2];
    const float* W1 = (const float*)d_in[3],  *b1 = (const float*)d_in[4];
    const float* g1 = (const float*)d_in[5],  *be1 = (const float*)d_in[6];
    const float* m1 = (const float*)d_in[7],  *v1 = (const float*)d_in[8];
    const float* W2 = (const float*)d_in[9],  *b2 = (const float*)d_in[10];
    const float* g2 = (const float*)d_in[11], *be2 = (const float*)d_in[12];
    const float* m2 = (const float*)d_in[13], *v2 = (const float*)d_in[14];
    const float* W3 = (const float*)d_in[15], *b3 = (const float*)d_in[16];
    const float* g3 = (const float*)d_in[17], *be3 = (const float*)d_in[18];
    const float* m3 = (const float*)d_in[19], *v3 = (const float*)d_in[20];
    const float* lw = (const float*)d_in[21], *lb = (const float*)d_in[22];
    float* out = (float*)d_out;

    float *p_Y0, *p_Y1, *p_Y2, *p_Z, *p_H1, *p_H2, *p_H3, *p_pool;
    int *p_degi, *p_cnt, *p_rowptr, *p_cursor;
    cudaGetSymbolAddress((void**)&p_degi,   g_degi);
    cudaGetSymbolAddress((void**)&p_cnt,    g_cnt);
    cudaGetSymbolAddress((void**)&p_rowptr, g_rowptr);
    cudaGetSymbolAddress((void**)&p_cursor, g_cursor);
    cudaGetSymbolAddress((void**)&p_Y0,     g_Y0);
    cudaGetSymbolAddress((void**)&p_Y1,     g_Y1);
    cudaGetSymbolAddress((void**)&p_Y2,     g_Y2);
    cudaGetSymbolAddress((void**)&p_Z,      g_Z);
    cudaGetSymbolAddress((void**)&p_H1,     g_H1);
    cudaGetSymbolAddress((void**)&p_H2,     g_H2);
    cudaGetSymbolAddress((void**)&p_H3,     g_H3);
    cudaGetSymbolAddress((void**)&p_pool,   g_pool);

    cudaMemsetAsync(p_degi, 0, NN * sizeof(int));
    cudaMemsetAsync(p_cnt,  0, NN * sizeof(int));
    cudaMemsetAsync(p_pool, 0, (GG * 16 + GG) * sizeof(float));

    int eb = (EE + 255) / 256;

    // ----- CSR build (shared by all props) -----
    k_degcnt<<<eb, 256>>>(ei);
    k_scan1<<<NBLK, SCAN_BLK>>>();
    k_scan2<<<1, 256>>>();
    k_scan3<<<(NN + 255) / 256, 256>>>();
    cudaMemcpyAsync(p_cursor, p_rowptr, NN * sizeof(int), cudaMemcpyDeviceToDevice);
    k_fill<<<eb, 256>>>(ei);

    int gm = (NN + 63) / 64;                 // GEMM blocks
    int gw32 = ((NN * 32) + 255) / 256;      // 32 threads/node
    int gw16 = ((NN * 16) + 255) / 256;      // 16 threads/node

    // ----- layer 1: 128 -> 64 -----
    // Z = Y1 + P(Y2);  H1 = act(bn(Y0 + P(Z)))
    k_prep<<<1, 256>>>(W1, b1, g1, be1, m1, v1, 128, 64, 192);
    k_gemmY<128, 64, 192, 4><<<gm, 256>>>(x, p_Y0, p_Y1, p_Y2);
    k_gath<64, 32, false><<<gw32, 256>>>(p_Y2, p_Y1, p_Z);
    k_gath<64, 32, true ><<<gw32, 256>>>(p_Z,  p_Y0, p_H1);

    // ----- layer 2: 64 -> 32 -----
    k_prep<<<1, 256>>>(W2, b2, g2, be2, m2, v2, 64, 32, 96);
    k_gemmY<64, 32, 96, 2><<<gm, 256>>>(p_H1, p_Y0, p_Y1, p_Y2);
    k_gath<32, 32, false><<<gw32, 256>>>(p_Y2, p_Y1, p_Z);
    k_gath<32, 32, true ><<<gw32, 256>>>(p_Z,  p_Y0, p_H2);

    // ----- layer 3: 32 -> 16 -----
    k_prep<<<1, 256>>>(W3, b3, g3, be3, m3, v3, 32, 16, 64);
    k_gemmY<32, 16, 64, 4><<<gm, 256>>>(p_H2, p_Y0, p_Y1, p_Y2);
    k_gath<16, 16, false><<<gw16, 256>>>(p_Y2, p_Y1, p_Z);
    k_gath<16, 16, true ><<<gw16, 256>>>(p_Z,  p_Y0, p_H3);

    // ----- pool + classifier -----
    {
        int threads = (NN + 15) / 16;
        int gb = (threads + 255) / 256;
        k_pool<<<gb, 256>>>(p_H3, batch);
    }
    k_final<<<1, 128>>>(lw, lb, out);
}